// round 5
// baseline (speedup 1.0000x reference)
#include <cuda_runtime.h>
#include <math_constants.h>

#define NB 128
#define N 1024
#define NITERS 20
#define GROUP 16
#define NGROUPS (NB / GROUP)
#define CTAS 512
#define LOG2E 1.44269504088896340736f

// s stored in LOG2 domain: s2 = (log_alpha + gumbel)/TEMP * log2(e).
// R, C are log2-domain normalizers; hot exp is a bare MUFU.EX2.
static __device__ float g_s[(size_t)NB * N * N];   // 512 MB
static __device__ float g_R[NB * N];
static __device__ float g_C[NB * N];
static __device__ unsigned g_cnt;                   // barrier arrivals
static __device__ volatile unsigned g_gen;          // barrier generation

__device__ __forceinline__ float ex2(float x) {
    float y;
    asm("ex2.approx.ftz.f32 %0, %1;" : "=f"(y) : "f"(x));
    return y;
}

// Software grid barrier. Safe because grid (512) <= guaranteed capacity
// (148 SMs x >=4 CTAs via __launch_bounds__(256,4) = 592).
__device__ __forceinline__ void gridbar() {
    __syncthreads();
    if (threadIdx.x == 0) {
        unsigned old = g_gen;             // pre-bump value: my arrival is required
        __threadfence();                  // my writes visible before signaling
        if (atomicAdd(&g_cnt, 1u) == CTAS - 1) {
            g_cnt = 0u;
            __threadfence();              // reset ordered before release
            atomicAdd((unsigned*)&g_gen, 1u);
        } else {
            while (g_gen == old) __nanosleep(32);
        }
        __threadfence();                  // acquire for post-barrier reads
    }
    __syncthreads();
}

// ---------------------------------------------------------------------------
// One persistent kernel per group of 16 batches (64 MB of s, L2-resident):
//   init -> B -> row_first -> B -> [row -> B]* col -> B ... -> final
// Cross-CTA-rewritten data (g_R, g_C) is read with __ldcg (L1 is not
// coherent across SMs within a launch). g_s is write-once pre-barrier.
// ---------------------------------------------------------------------------
__global__ void __launch_bounds__(256, 4) gs_group(const float* __restrict__ la,
                                                   const float* __restrict__ noise,
                                                   float* __restrict__ out,
                                                   int b0) {
    __shared__ float sbuf[N];          // staged C (row pass) or R (col pass)
    __shared__ float part[8][33];
    const int tid = threadIdx.x, lane = tid & 31, w = tid >> 5;
    const int cta = blockIdx.x;

    // ---------------- init: s2 = (la + gumbel)/TEMP * log2e; C = 0 ---------
    {
        const float EPS = 1e-20f;
        const float SC = 10.0f * LOG2E;
        const size_t nvec = (size_t)GROUP * N * N / 4;
        const size_t base = (size_t)b0 * N * N;
        for (size_t v = (size_t)cta * 256 + tid; v < nvec; v += (size_t)CTAS * 256) {
            size_t e = base + v * 4;
            float4 a = *reinterpret_cast<const float4*>(la + e);
            float4 u = *reinterpret_cast<const float4*>(noise + e);
            float4 s;
            s.x = (a.x - logf(EPS - logf(u.x + EPS))) * SC;
            s.y = (a.y - logf(EPS - logf(u.y + EPS))) * SC;
            s.z = (a.z - logf(EPS - logf(u.z + EPS))) * SC;
            s.w = (a.w - logf(EPS - logf(u.w + EPS))) * SC;
            *reinterpret_cast<float4*>(g_s + e) = s;
        }
        int t0 = cta * 256 + tid;
        if (t0 < GROUP * N) g_C[(size_t)b0 * N + t0] = 0.0f;
    }
    gridbar();

    // ---------------- row_first (C = 0): exact per-row max ------------------
    for (int chunk = cta; chunk < GROUP * 128; chunk += CTAS) {
        int b = b0 + (chunk >> 7);
        int row = ((chunk & 127) << 3) + w;
        const float4* __restrict__ srow =
            reinterpret_cast<const float4*>(g_s + ((size_t)b * N + row) * N);
        float4 sv[8];
#pragma unroll
        for (int k = 0; k < 8; k++) sv[k] = srow[k * 32 + lane];
        float m = -CUDART_INF_F;
#pragma unroll
        for (int k = 0; k < 8; k++)
            m = fmaxf(m, fmaxf(fmaxf(sv[k].x, sv[k].y), fmaxf(sv[k].z, sv[k].w)));
#pragma unroll
        for (int o = 16; o; o >>= 1) m = fmaxf(m, __shfl_xor_sync(~0u, m, o));
        float a0 = 0.f, a1 = 0.f;
#pragma unroll
        for (int k = 0; k < 8; k++) {
            a0 += ex2(sv[k].x - m) + ex2(sv[k].y - m);
            a1 += ex2(sv[k].z - m) + ex2(sv[k].w - m);
        }
        float sum = a0 + a1;
#pragma unroll
        for (int o = 16; o; o >>= 1) sum += __shfl_xor_sync(~0u, sum, o);
        if (lane == 0) g_R[(size_t)b * N + row] = m + __log2f(sum);
    }
    gridbar();

    // ---------------- 20 iterations ----------------------------------------
    for (int t = 0; t < NITERS; t++) {
        if (t > 0) {
            // Row pass (shift trick: s - C <= R_prev, exp args <= 0).
            for (int chunk = cta; chunk < GROUP * 128; chunk += CTAS) {
                int b = b0 + (chunk >> 7);
                int row = ((chunk & 127) << 3) + w;
                reinterpret_cast<float4*>(sbuf)[tid] =
                    __ldcg(reinterpret_cast<const float4*>(g_C + (size_t)b * N) + tid);
                __syncthreads();
                const float4* __restrict__ srow =
                    reinterpret_cast<const float4*>(g_s + ((size_t)b * N + row) * N);
                float rprev = __ldcg(&g_R[(size_t)b * N + row]);
                float4 sv[8];
#pragma unroll
                for (int k = 0; k < 8; k++) sv[k] = srow[k * 32 + lane];
                const float4* scv = reinterpret_cast<const float4*>(sbuf);
                float a0 = 0.f, a1 = 0.f;
#pragma unroll
                for (int k = 0; k < 8; k++) {
                    float4 cv = scv[k * 32 + lane];
                    a0 += ex2(sv[k].x - cv.x - rprev) + ex2(sv[k].y - cv.y - rprev);
                    a1 += ex2(sv[k].z - cv.z - rprev) + ex2(sv[k].w - cv.w - rprev);
                }
                float sum = a0 + a1;
#pragma unroll
                for (int o = 16; o; o >>= 1) sum += __shfl_xor_sync(~0u, sum, o);
                if (lane == 0) g_R[(size_t)b * N + row] = rprev + __log2f(sum);
                __syncthreads();   // protect sbuf before next chunk reload
            }
            gridbar();
        }
        // Col pass (shift trick: s - R <= C_prev). One 32-col chunk per CTA.
        {
            int b = b0 + (cta >> 5);
            int j = ((cta & 31) << 5) + lane;
            reinterpret_cast<float4*>(sbuf)[tid] =
                __ldcg(reinterpret_cast<const float4*>(g_R + (size_t)b * N) + tid);
            __syncthreads();
            float cprev = __ldcg(&g_C[(size_t)b * N + j]);
            const float* __restrict__ sp = g_s + (size_t)b * N * N + j;
            int i0 = w << 7;   // 8 warps x 128-row stripes
            float acc0 = 0.f, acc1 = 0.f;
#pragma unroll 2
            for (int ii = 0; ii < 128; ii += 8) {
                float v[8];
#pragma unroll
                for (int q = 0; q < 8; q++) v[q] = sp[(size_t)(i0 + ii + q) * N];
#pragma unroll
                for (int q = 0; q < 8; q += 2) {
                    acc0 += ex2(v[q]     - sbuf[i0 + ii + q]     - cprev);
                    acc1 += ex2(v[q + 1] - sbuf[i0 + ii + q + 1] - cprev);
                }
            }
            part[w][lane] = acc0 + acc1;
            __syncthreads();
            if (w == 0) {
                float tsum = 0.f;
#pragma unroll
                for (int k = 0; k < 8; k++) tsum += part[k][lane];
                g_C[(size_t)b * N + j] = cprev + __log2f(tsum);
            }
        }
        gridbar();
    }

    // ---------------- final: out = exp2(s - R - C) --------------------------
    {
        const size_t nvec = (size_t)GROUP * N * N / 4;
        const size_t base = (size_t)b0 * N * N;
        for (size_t v = (size_t)cta * 256 + tid; v < nvec; v += (size_t)CTAS * 256) {
            size_t e = base + v * 4;
            int row = (int)(e >> 10);
            int b = row >> 10;
            int j = (int)(e & (N - 1));
            float r = __ldcg(&g_R[row]);
            float4 c = __ldcg(reinterpret_cast<const float4*>(g_C + (size_t)b * N + j));
            float4 sv = *reinterpret_cast<const float4*>(g_s + e);
            float4 o;
            o.x = ex2(sv.x - r - c.x);
            o.y = ex2(sv.y - r - c.y);
            o.z = ex2(sv.z - r - c.z);
            o.w = ex2(sv.w - r - c.w);
            *reinterpret_cast<float4*>(out + e) = o;
        }
    }
}

// ---------------------------------------------------------------------------
// 8 launches total: one persistent kernel per 16-batch group.
// ---------------------------------------------------------------------------
extern "C" void kernel_launch(void* const* d_in, const int* in_sizes, int n_in,
                              void* d_out, int out_size) {
    const float* la = (const float*)d_in[0];
    const float* noise = (const float*)d_in[1];
    float* out = (float*)d_out;
    for (int g = 0; g < NGROUPS; g++)
        gs_group<<<CTAS, 256>>>(la, noise, out, g * GROUP);
}

// round 6
// speedup vs baseline: 1.3360x; 1.3360x over previous
#include <cuda_runtime.h>
#include <cuda_fp16.h>
#include <math_constants.h>

#define NB 128
#define N 1024
#define NITERS 20
#define GROUP 16
#define NGROUPS (NB / GROUP)
#define LOG2E 1.44269504088896340736f

// s in LOG2 domain (fp32, first iteration only); s_shift = s - R1 - C1 in fp16
// for iterations 2..20 and the final pass. R/C absolute (fp32), Rr/Cr relative.
static __device__ float  g_s[(size_t)NB * N * N];    // 512 MB
static __device__ __half g_h[(size_t)NB * N * N];    // 256 MB
static __device__ float g_R[NB * N], g_C[NB * N];    // absolute (iter 1)
static __device__ float g_Rr[NB * N], g_Cr[NB * N];  // relative (iters 2+)

__device__ __forceinline__ float ex2(float x) {
    float y;
    asm("ex2.approx.ftz.f32 %0, %1;" : "=f"(y) : "f"(x));
    return y;
}

// ---------------------------------------------------------------------------
// Init: s2 = (la + gumbel)/TEMP * log2e. Accurate logf for the inner log
// (u near 1 -> catastrophic cancellation with a fast log); __logf outside.
// ---------------------------------------------------------------------------
__global__ void __launch_bounds__(256) gs_init(const float* __restrict__ la,
                                               const float* __restrict__ noise,
                                               int b0) {
    const float EPS = 1e-20f;
    const float SC = 10.0f * LOG2E;
    size_t tid = (size_t)blockIdx.x * 256 + threadIdx.x;
    size_t e = (size_t)b0 * N * N + tid * 4;
    float4 a = *reinterpret_cast<const float4*>(la + e);
    float4 u = *reinterpret_cast<const float4*>(noise + e);
    float4 s;
    s.x = (a.x - __logf(EPS - logf(u.x + EPS))) * SC;
    s.y = (a.y - __logf(EPS - logf(u.y + EPS))) * SC;
    s.z = (a.z - __logf(EPS - logf(u.z + EPS))) * SC;
    s.w = (a.w - __logf(EPS - logf(u.w + EPS))) * SC;
    *reinterpret_cast<float4*>(g_s + e) = s;
}

// ---------------------------------------------------------------------------
// Iter-1 row pass (C=0): exact per-row max; warp per row, row in registers.
// ---------------------------------------------------------------------------
__global__ void __launch_bounds__(256) gs_row_first(int b0) {
    int lane = threadIdx.x & 31, w = threadIdx.x >> 5;
    int rglob = b0 * N + blockIdx.x * 8 + w;
    const float4* __restrict__ srow =
        reinterpret_cast<const float4*>(g_s + (size_t)rglob * N);
    float4 sv[8];
#pragma unroll
    for (int k = 0; k < 8; k++) sv[k] = srow[k * 32 + lane];
    float m = -CUDART_INF_F;
#pragma unroll
    for (int k = 0; k < 8; k++)
        m = fmaxf(m, fmaxf(fmaxf(sv[k].x, sv[k].y), fmaxf(sv[k].z, sv[k].w)));
#pragma unroll
    for (int o = 16; o; o >>= 1) m = fmaxf(m, __shfl_xor_sync(~0u, m, o));
    float a0 = 0.f, a1 = 0.f;
#pragma unroll
    for (int k = 0; k < 8; k++) {
        a0 += ex2(sv[k].x - m) + ex2(sv[k].y - m);
        a1 += ex2(sv[k].z - m) + ex2(sv[k].w - m);
    }
    float sum = a0 + a1;
#pragma unroll
    for (int o = 16; o; o >>= 1) sum += __shfl_xor_sync(~0u, sum, o);
    if (lane == 0) g_R[rglob] = m + __log2f(sum);
}

// ---------------------------------------------------------------------------
// Iter-1 col pass (fp32): C1 = LSE_i(s - R1); shift trick (args <= 0 since
// C_prev = 0 and s - R1 <= 0... actually s - R1 <= C_prev=0 by LSE bound).
// ---------------------------------------------------------------------------
__global__ void __launch_bounds__(512) gs_col_first(int b0) {
    __shared__ float sr[N];
    __shared__ float part[16][33];
    int tid = threadIdx.x, lane = tid & 31, w = tid >> 5;
    int b = b0 + blockIdx.y;
    int j = blockIdx.x * 32 + lane;
    if (tid < 256)
        reinterpret_cast<float4*>(sr)[tid] =
            reinterpret_cast<const float4*>(g_R + (size_t)b * N)[tid];
    __syncthreads();
    const float* __restrict__ sp = g_s + (size_t)b * N * N + j;
    int i0 = w * 64;
    float acc0 = 0.f, acc1 = 0.f;
#pragma unroll
    for (int ii = 0; ii < 64; ii += 8) {
        float v[8];
#pragma unroll
        for (int q = 0; q < 8; q++) v[q] = sp[(size_t)(i0 + ii + q) * N];
#pragma unroll
        for (int q = 0; q < 8; q += 2) {
            acc0 += ex2(v[q]     - sr[i0 + ii + q]);
            acc1 += ex2(v[q + 1] - sr[i0 + ii + q + 1]);
        }
    }
    part[w][lane] = acc0 + acc1;
    __syncthreads();
    if (w == 0) {
        float t = 0.f;
#pragma unroll
        for (int k = 0; k < 16; k++) t += part[k][lane];
        g_C[(size_t)b * N + j] = __log2f(t);
    }
}

// ---------------------------------------------------------------------------
// Iter-2 row pass FUSED with fp16 pack: reads s2 (fp32) once, writes
// s_shift = s - R1_i - C1_j as half, computes Rr = log2(rowsum), zeros Cr.
// ---------------------------------------------------------------------------
__global__ void __launch_bounds__(256) gs_row_pack(int b0) {
    __shared__ float sc[N];
    int tid = threadIdx.x, lane = tid & 31, w = tid >> 5;
    int b = b0 + (blockIdx.x >> 7);
    int row = ((blockIdx.x & 127) << 3) + w;
    reinterpret_cast<float4*>(sc)[tid] =
        reinterpret_cast<const float4*>(g_C + (size_t)b * N)[tid];
    if ((blockIdx.x & 127) == 0) {
        float4 z = {0.f, 0.f, 0.f, 0.f};
        reinterpret_cast<float4*>(g_Cr + (size_t)b * N)[tid] = z;
    }
    __syncthreads();

    const float4* __restrict__ srow =
        reinterpret_cast<const float4*>(g_s + ((size_t)b * N + row) * N);
    float r1 = g_R[(size_t)b * N + row];
    float4 sv[8];
#pragma unroll
    for (int k = 0; k < 8; k++) sv[k] = srow[k * 32 + lane];

    uint2* hrow = reinterpret_cast<uint2*>(g_h + ((size_t)b * N + row) * N);
    const float4* scv = reinterpret_cast<const float4*>(sc);
    float a0 = 0.f, a1 = 0.f;
#pragma unroll
    for (int k = 0; k < 8; k++) {
        int idx = k * 32 + lane;
        float4 cv = scv[idx];
        float ax = sv[k].x - cv.x - r1, ay = sv[k].y - cv.y - r1;
        float az = sv[k].z - cv.z - r1, aw = sv[k].w - cv.w - r1;
        a0 += ex2(ax) + ex2(ay);
        a1 += ex2(az) + ex2(aw);
        __half2 h01 = __floats2half2_rn(ax, ay);
        __half2 h23 = __floats2half2_rn(az, aw);
        uint2 pv;
        pv.x = *reinterpret_cast<unsigned*>(&h01);
        pv.y = *reinterpret_cast<unsigned*>(&h23);
        hrow[idx] = pv;
    }
    float sum = a0 + a1;
#pragma unroll
    for (int o = 16; o; o >>= 1) sum += __shfl_xor_sync(~0u, sum, o);
    if (lane == 0) g_Rr[(size_t)b * N + row] = __log2f(sum);
}

// ---------------------------------------------------------------------------
// fp16 row pass, iters 3..20 (shift trick in shifted domain, args <= 0).
// Storage fp16, arithmetic fp32.
// ---------------------------------------------------------------------------
__global__ void __launch_bounds__(256) gs_row_h(int b0) {
    __shared__ float sc[N];
    int tid = threadIdx.x, lane = tid & 31, w = tid >> 5;
    int b = b0 + (blockIdx.x >> 7);
    int row = ((blockIdx.x & 127) << 3) + w;
    reinterpret_cast<float4*>(sc)[tid] =
        reinterpret_cast<const float4*>(g_Cr + (size_t)b * N)[tid];
    __syncthreads();

    const uint4* __restrict__ hrow =
        reinterpret_cast<const uint4*>(g_h + ((size_t)b * N + row) * N);
    float rprev = g_Rr[(size_t)b * N + row];
    uint4 hv[4];
#pragma unroll
    for (int k = 0; k < 4; k++) hv[k] = hrow[k * 32 + lane];

    const float4* scv = reinterpret_cast<const float4*>(sc);
    float a0 = 0.f, a1 = 0.f;
#pragma unroll
    for (int k = 0; k < 4; k++) {
        int i = k * 32 + lane;
        float4 c0 = scv[2 * i], c1 = scv[2 * i + 1];
        float2 f0 = __half22float2(*reinterpret_cast<__half2*>(&hv[k].x));
        float2 f1 = __half22float2(*reinterpret_cast<__half2*>(&hv[k].y));
        float2 f2 = __half22float2(*reinterpret_cast<__half2*>(&hv[k].z));
        float2 f3 = __half22float2(*reinterpret_cast<__half2*>(&hv[k].w));
        a0 += ex2(f0.x - c0.x - rprev) + ex2(f0.y - c0.y - rprev);
        a1 += ex2(f1.x - c0.z - rprev) + ex2(f1.y - c0.w - rprev);
        a0 += ex2(f2.x - c1.x - rprev) + ex2(f2.y - c1.y - rprev);
        a1 += ex2(f3.x - c1.z - rprev) + ex2(f3.y - c1.w - rprev);
    }
    float sum = a0 + a1;
#pragma unroll
    for (int o = 16; o; o >>= 1) sum += __shfl_xor_sync(~0u, sum, o);
    if (lane == 0) g_Rr[(size_t)b * N + row] = rprev + __log2f(sum);
}

// ---------------------------------------------------------------------------
// fp16 col pass: 64 cols/block (half2 per lane, full 128B lines),
// 16 warps x 64-row stripes, Rr in SMEM.
// ---------------------------------------------------------------------------
__global__ void __launch_bounds__(512) gs_col_h(int b0) {
    __shared__ float sr[N];
    __shared__ float part[16][66];
    int tid = threadIdx.x, lane = tid & 31, w = tid >> 5;
    int b = b0 + blockIdx.y;
    int j0 = blockIdx.x * 64;
    if (tid < 256)
        reinterpret_cast<float4*>(sr)[tid] =
            reinterpret_cast<const float4*>(g_Rr + (size_t)b * N)[tid];
    __syncthreads();

    float2 cp = *reinterpret_cast<const float2*>(g_Cr + (size_t)b * N + j0 + 2 * lane);
    const __half2* __restrict__ hp =
        reinterpret_cast<const __half2*>(g_h + (size_t)b * N * N + j0) + lane;
    int i0 = w * 64;
    float ax = 0.f, ay = 0.f;
#pragma unroll
    for (int ii = 0; ii < 64; ii += 8) {
        __half2 v[8];
#pragma unroll
        for (int q = 0; q < 8; q++) v[q] = hp[(size_t)(i0 + ii + q) * (N / 2)];
#pragma unroll
        for (int q = 0; q < 8; q++) {
            float rr = sr[i0 + ii + q];
            float2 f = __half22float2(v[q]);
            ax += ex2(f.x - rr - cp.x);
            ay += ex2(f.y - rr - cp.y);
        }
    }
    part[w][2 * lane] = ax;
    part[w][2 * lane + 1] = ay;
    __syncthreads();
    if (tid < 64) {
        float t = 0.f;
#pragma unroll
        for (int k = 0; k < 16; k++) t += part[k][tid];
        size_t cj = (size_t)b * N + j0 + tid;
        g_Cr[cj] = g_Cr[cj] + __log2f(t);
    }
}

// ---------------------------------------------------------------------------
// Final: out = exp2(s_shift - Rr - Cr). (R1, C1 already baked into s_shift.)
// ---------------------------------------------------------------------------
__global__ void __launch_bounds__(256) gs_final(float* __restrict__ out, int b0) {
    size_t t8 = (size_t)blockIdx.x * 256 + threadIdx.x;
    size_t e = (size_t)b0 * N * N + t8 * 8;
    int row = (int)(e >> 10);
    int b = row >> 10;
    int j = (int)(e & (N - 1));
    float r = g_Rr[row];
    float4 c0 = *reinterpret_cast<const float4*>(g_Cr + (size_t)b * N + j);
    float4 c1 = *reinterpret_cast<const float4*>(g_Cr + (size_t)b * N + j + 4);
    uint4 hv = *reinterpret_cast<const uint4*>(g_h + e);
    float2 f0 = __half22float2(*reinterpret_cast<__half2*>(&hv.x));
    float2 f1 = __half22float2(*reinterpret_cast<__half2*>(&hv.y));
    float2 f2 = __half22float2(*reinterpret_cast<__half2*>(&hv.z));
    float2 f3 = __half22float2(*reinterpret_cast<__half2*>(&hv.w));
    float4 o0, o1;
    o0.x = ex2(f0.x - r - c0.x); o0.y = ex2(f0.y - r - c0.y);
    o0.z = ex2(f1.x - r - c0.z); o0.w = ex2(f1.y - r - c0.w);
    o1.x = ex2(f2.x - r - c1.x); o1.y = ex2(f2.y - r - c1.y);
    o1.z = ex2(f3.x - r - c1.z); o1.w = ex2(f3.y - r - c1.w);
    *reinterpret_cast<float4*>(out + e) = o0;
    *reinterpret_cast<float4*>(out + e + 4) = o1;
}

// ---------------------------------------------------------------------------
// 8 groups of 16 batches; iteration working set after pack = 32 MB (L2-hot).
// ---------------------------------------------------------------------------
extern "C" void kernel_launch(void* const* d_in, const int* in_sizes, int n_in,
                              void* d_out, int out_size) {
    const float* la = (const float*)d_in[0];
    const float* noise = (const float*)d_in[1];
    float* out = (float*)d_out;

    for (int g = 0; g < NGROUPS; g++) {
        int b0 = g * GROUP;
        gs_init<<<(GROUP * N * N) / (256 * 4), 256>>>(la, noise, b0);
        gs_row_first<<<(GROUP * N) / 8, 256>>>(b0);
        gs_col_first<<<dim3(N / 32, GROUP), 512>>>(b0);
        gs_row_pack<<<(GROUP * N) / 8, 256>>>(b0);      // iter-2 row + pack
        gs_col_h<<<dim3(N / 64, GROUP), 512>>>(b0);     // iter-2 col
        for (int t = 3; t <= NITERS; t++) {
            gs_row_h<<<(GROUP * N) / 8, 256>>>(b0);
            gs_col_h<<<dim3(N / 64, GROUP), 512>>>(b0);
        }
        gs_final<<<(GROUP * N * N) / (256 * 8), 256>>>(out, b0);
    }
}

// round 7
// speedup vs baseline: 1.3644x; 1.0212x over previous
#include <cuda_runtime.h>
#include <cuda_fp16.h>
#include <math_constants.h>

#define NB 128
#define N 1024
#define NITERS 20
#define GROUP 16
#define NGROUPS (NB / GROUP)
#define LOG2E 1.44269504088896340736f

// s in LOG2 domain (fp32, first iteration only); s_shift = s - R1 - C1 in fp16
// for iterations 2..20 and the final pass. R/C absolute (iter 1), Rr/Cr relative.
static __device__ float  g_s[(size_t)NB * N * N];    // 512 MB
static __device__ __half g_h[(size_t)NB * N * N];    // 256 MB
static __device__ float g_R[NB * N], g_C[NB * N];
static __device__ float g_Rr[NB * N], g_Cr[NB * N];

__device__ __forceinline__ float ex2(float x) {
    float y;
    asm("ex2.approx.ftz.f32 %0, %1;" : "=f"(y) : "f"(x));
    return y;
}

// ---------------------------------------------------------------------------
// FUSED init + iter-1 row pass. Warp per row: read la/noise rows directly,
// Gumbel transform in registers (accurate logf for the inner log — its
// extremes dominate the row max), write s once, compute R1 with exact max.
// ---------------------------------------------------------------------------
__global__ void __launch_bounds__(256) gs_init_row(const float* __restrict__ la,
                                                   const float* __restrict__ noise,
                                                   int b0) {
    const float EPS = 1e-20f;
    const float SC = 10.0f * LOG2E;
    int lane = threadIdx.x & 31, w = threadIdx.x >> 5;
    int rglob = b0 * N + blockIdx.x * 8 + w;
    const float4* __restrict__ arow =
        reinterpret_cast<const float4*>(la + (size_t)rglob * N);
    const float4* __restrict__ urow =
        reinterpret_cast<const float4*>(noise + (size_t)rglob * N);
    float4* __restrict__ srow = reinterpret_cast<float4*>(g_s + (size_t)rglob * N);

    float4 sv[8];
#pragma unroll
    for (int k = 0; k < 8; k++) {
        float4 a = arow[k * 32 + lane];
        float4 u = urow[k * 32 + lane];
        sv[k].x = (a.x - __logf(EPS - logf(u.x + EPS))) * SC;
        sv[k].y = (a.y - __logf(EPS - logf(u.y + EPS))) * SC;
        sv[k].z = (a.z - __logf(EPS - logf(u.z + EPS))) * SC;
        sv[k].w = (a.w - __logf(EPS - logf(u.w + EPS))) * SC;
        srow[k * 32 + lane] = sv[k];
    }
    float m = -CUDART_INF_F;
#pragma unroll
    for (int k = 0; k < 8; k++)
        m = fmaxf(m, fmaxf(fmaxf(sv[k].x, sv[k].y), fmaxf(sv[k].z, sv[k].w)));
#pragma unroll
    for (int o = 16; o; o >>= 1) m = fmaxf(m, __shfl_xor_sync(~0u, m, o));
    float a0 = 0.f, a1 = 0.f;
#pragma unroll
    for (int k = 0; k < 8; k++) {
        a0 += ex2(sv[k].x - m) + ex2(sv[k].y - m);
        a1 += ex2(sv[k].z - m) + ex2(sv[k].w - m);
    }
    float sum = a0 + a1;
#pragma unroll
    for (int o = 16; o; o >>= 1) sum += __shfl_xor_sync(~0u, sum, o);
    if (lane == 0) g_R[rglob] = m + __log2f(sum);
}

// ---------------------------------------------------------------------------
// Iter-1 col pass (fp32): C1 = LSE_i(s - R1); args <= 0 by the LSE bound.
// ---------------------------------------------------------------------------
__global__ void __launch_bounds__(512) gs_col_first(int b0) {
    __shared__ float sr[N];
    __shared__ float part[16][33];
    int tid = threadIdx.x, lane = tid & 31, w = tid >> 5;
    int b = b0 + blockIdx.y;
    int j = blockIdx.x * 32 + lane;
    if (tid < 256)
        reinterpret_cast<float4*>(sr)[tid] =
            reinterpret_cast<const float4*>(g_R + (size_t)b * N)[tid];
    __syncthreads();
    const float* __restrict__ sp = g_s + (size_t)b * N * N + j;
    int i0 = w * 64;
    float acc0 = 0.f, acc1 = 0.f;
#pragma unroll
    for (int ii = 0; ii < 64; ii += 8) {
        float v[8];
#pragma unroll
        for (int q = 0; q < 8; q++) v[q] = sp[(size_t)(i0 + ii + q) * N];
#pragma unroll
        for (int q = 0; q < 8; q += 2) {
            acc0 += ex2(v[q]     - sr[i0 + ii + q]);
            acc1 += ex2(v[q + 1] - sr[i0 + ii + q + 1]);
        }
    }
    part[w][lane] = acc0 + acc1;
    __syncthreads();
    if (w == 0) {
        float t = 0.f;
#pragma unroll
        for (int k = 0; k < 16; k++) t += part[k][lane];
        g_C[(size_t)b * N + j] = __log2f(t);
    }
}

// ---------------------------------------------------------------------------
// Iter-2 row pass FUSED with fp16 pack. Two 512-col halves (4 float4 in
// flight) to keep regs low; __ldcs on s (last use -> evict-first).
// Writes s_shift = s - R1 - C1 (<= 0) as half; Rr = log2(rowsum); Cr = 0.
// ---------------------------------------------------------------------------
__global__ void __launch_bounds__(256) gs_row_pack(int b0) {
    __shared__ float sc[N];
    int tid = threadIdx.x, lane = tid & 31, w = tid >> 5;
    int b = b0 + (blockIdx.x >> 7);
    int row = ((blockIdx.x & 127) << 3) + w;
    reinterpret_cast<float4*>(sc)[tid] =
        reinterpret_cast<const float4*>(g_C + (size_t)b * N)[tid];
    if ((blockIdx.x & 127) == 0) {
        float4 z = {0.f, 0.f, 0.f, 0.f};
        reinterpret_cast<float4*>(g_Cr + (size_t)b * N)[tid] = z;
    }
    __syncthreads();

    const float4* __restrict__ srow =
        reinterpret_cast<const float4*>(g_s + ((size_t)b * N + row) * N);
    uint2* hrow = reinterpret_cast<uint2*>(g_h + ((size_t)b * N + row) * N);
    const float4* scv = reinterpret_cast<const float4*>(sc);
    float r1 = g_R[(size_t)b * N + row];

    float a0 = 0.f, a1 = 0.f;
#pragma unroll
    for (int h = 0; h < 2; h++) {
        float4 sv[4];
#pragma unroll
        for (int k = 0; k < 4; k++) sv[k] = __ldcs(&srow[h * 128 + k * 32 + lane]);
#pragma unroll
        for (int k = 0; k < 4; k++) {
            int idx = h * 128 + k * 32 + lane;
            float4 cv = scv[idx];
            float ax = sv[k].x - cv.x - r1, ay = sv[k].y - cv.y - r1;
            float az = sv[k].z - cv.z - r1, aw = sv[k].w - cv.w - r1;
            a0 += ex2(ax) + ex2(ay);
            a1 += ex2(az) + ex2(aw);
            __half2 h01 = __floats2half2_rn(ax, ay);
            __half2 h23 = __floats2half2_rn(az, aw);
            uint2 pv;
            pv.x = *reinterpret_cast<unsigned*>(&h01);
            pv.y = *reinterpret_cast<unsigned*>(&h23);
            hrow[idx] = pv;
        }
    }
    float sum = a0 + a1;
#pragma unroll
    for (int o = 16; o; o >>= 1) sum += __shfl_xor_sync(~0u, sum, o);
    if (lane == 0) g_Rr[(size_t)b * N + row] = __log2f(sum);
}

// ---------------------------------------------------------------------------
// fp16 row pass, iters 3..20 (shifted domain, args <= 0). fp32 arithmetic.
// ---------------------------------------------------------------------------
__global__ void __launch_bounds__(256) gs_row_h(int b0) {
    __shared__ float sc[N];
    int tid = threadIdx.x, lane = tid & 31, w = tid >> 5;
    int b = b0 + (blockIdx.x >> 7);
    int row = ((blockIdx.x & 127) << 3) + w;
    reinterpret_cast<float4*>(sc)[tid] =
        reinterpret_cast<const float4*>(g_Cr + (size_t)b * N)[tid];
    __syncthreads();

    const uint4* __restrict__ hrow =
        reinterpret_cast<const uint4*>(g_h + ((size_t)b * N + row) * N);
    float rprev = g_Rr[(size_t)b * N + row];
    uint4 hv[4];
#pragma unroll
    for (int k = 0; k < 4; k++) hv[k] = hrow[k * 32 + lane];

    const float4* scv = reinterpret_cast<const float4*>(sc);
    float a0 = 0.f, a1 = 0.f;
#pragma unroll
    for (int k = 0; k < 4; k++) {
        int i = k * 32 + lane;
        float4 c0 = scv[2 * i], c1 = scv[2 * i + 1];
        float2 f0 = __half22float2(*reinterpret_cast<__half2*>(&hv[k].x));
        float2 f1 = __half22float2(*reinterpret_cast<__half2*>(&hv[k].y));
        float2 f2 = __half22float2(*reinterpret_cast<__half2*>(&hv[k].z));
        float2 f3 = __half22float2(*reinterpret_cast<__half2*>(&hv[k].w));
        a0 += ex2(f0.x - c0.x - rprev) + ex2(f0.y - c0.y - rprev);
        a1 += ex2(f1.x - c0.z - rprev) + ex2(f1.y - c0.w - rprev);
        a0 += ex2(f2.x - c1.x - rprev) + ex2(f2.y - c1.y - rprev);
        a1 += ex2(f3.x - c1.z - rprev) + ex2(f3.y - c1.w - rprev);
    }
    float sum = a0 + a1;
#pragma unroll
    for (int o = 16; o; o >>= 1) sum += __shfl_xor_sync(~0u, sum, o);
    if (lane == 0) g_Rr[(size_t)b * N + row] = rprev + __log2f(sum);
}

// ---------------------------------------------------------------------------
// fp16 col pass: 64 cols/block (half2 per lane), 16 warps x 64-row stripes.
// ---------------------------------------------------------------------------
__global__ void __launch_bounds__(512) gs_col_h(int b0) {
    __shared__ float sr[N];
    __shared__ float part[16][66];
    int tid = threadIdx.x, lane = tid & 31, w = tid >> 5;
    int b = b0 + blockIdx.y;
    int j0 = blockIdx.x * 64;
    if (tid < 256)
        reinterpret_cast<float4*>(sr)[tid] =
            reinterpret_cast<const float4*>(g_Rr + (size_t)b * N)[tid];
    __syncthreads();

    float2 cp = *reinterpret_cast<const float2*>(g_Cr + (size_t)b * N + j0 + 2 * lane);
    const __half2* __restrict__ hp =
        reinterpret_cast<const __half2*>(g_h + (size_t)b * N * N + j0) + lane;
    int i0 = w * 64;
    float ax = 0.f, ay = 0.f;
#pragma unroll
    for (int ii = 0; ii < 64; ii += 8) {
        __half2 v[8];
#pragma unroll
        for (int q = 0; q < 8; q++) v[q] = hp[(size_t)(i0 + ii + q) * (N / 2)];
#pragma unroll
        for (int q = 0; q < 8; q++) {
            float rr = sr[i0 + ii + q];
            float2 f = __half22float2(v[q]);
            ax += ex2(f.x - rr - cp.x);
            ay += ex2(f.y - rr - cp.y);
        }
    }
    part[w][2 * lane] = ax;
    part[w][2 * lane + 1] = ay;
    __syncthreads();
    if (tid < 64) {
        float t = 0.f;
#pragma unroll
        for (int k = 0; k < 16; k++) t += part[k][tid];
        size_t cj = (size_t)b * N + j0 + tid;
        g_Cr[cj] = g_Cr[cj] + __log2f(t);
    }
}

// ---------------------------------------------------------------------------
// Final: out = exp2(s_shift - Rr - Cr). (R1, C1 baked into s_shift.)
// ---------------------------------------------------------------------------
__global__ void __launch_bounds__(256) gs_final(float* __restrict__ out, int b0) {
    size_t t8 = (size_t)blockIdx.x * 256 + threadIdx.x;
    size_t e = (size_t)b0 * N * N + t8 * 8;
    int row = (int)(e >> 10);
    int b = row >> 10;
    int j = (int)(e & (N - 1));
    float r = g_Rr[row];
    float4 c0 = *reinterpret_cast<const float4*>(g_Cr + (size_t)b * N + j);
    float4 c1 = *reinterpret_cast<const float4*>(g_Cr + (size_t)b * N + j + 4);
    uint4 hv = __ldcs(reinterpret_cast<const uint4*>(g_h + e));
    float2 f0 = __half22float2(*reinterpret_cast<__half2*>(&hv.x));
    float2 f1 = __half22float2(*reinterpret_cast<__half2*>(&hv.y));
    float2 f2 = __half22float2(*reinterpret_cast<__half2*>(&hv.z));
    float2 f3 = __half22float2(*reinterpret_cast<__half2*>(&hv.w));
    float4 o0, o1;
    o0.x = ex2(f0.x - r - c0.x); o0.y = ex2(f0.y - r - c0.y);
    o0.z = ex2(f1.x - r - c0.z); o0.w = ex2(f1.y - r - c0.w);
    o1.x = ex2(f2.x - r - c1.x); o1.y = ex2(f2.y - r - c1.y);
    o1.z = ex2(f3.x - r - c1.z); o1.w = ex2(f3.y - r - c1.w);
    *reinterpret_cast<float4*>(out + e) = o0;
    *reinterpret_cast<float4*>(out + e + 4) = o1;
}

// ---------------------------------------------------------------------------
// 8 groups of 16 batches; fp16 iteration working set = 32 MB (L2-hot).
// ---------------------------------------------------------------------------
extern "C" void kernel_launch(void* const* d_in, const int* in_sizes, int n_in,
                              void* d_out, int out_size) {
    const float* la = (const float*)d_in[0];
    const float* noise = (const float*)d_in[1];
    float* out = (float*)d_out;

    for (int g = 0; g < NGROUPS; g++) {
        int b0 = g * GROUP;
        gs_init_row<<<(GROUP * N) / 8, 256>>>(la, noise, b0);   // init + iter-1 row
        gs_col_first<<<dim3(N / 32, GROUP), 512>>>(b0);         // iter-1 col
        gs_row_pack<<<(GROUP * N) / 8, 256>>>(b0);              // iter-2 row + pack
        gs_col_h<<<dim3(N / 64, GROUP), 512>>>(b0);             // iter-2 col
        for (int t = 3; t <= NITERS; t++) {
            gs_row_h<<<(GROUP * N) / 8, 256>>>(b0);
            gs_col_h<<<dim3(N / 64, GROUP), 512>>>(b0);
        }
        gs_final<<<(GROUP * N * N) / (256 * 8), 256>>>(out, b0);
    }
}